// round 16
// baseline (speedup 1.0000x reference)
#include <cuda_runtime.h>
#include <cuda_fp16.h>
#include <cstdint>
#include <math.h>

// Problem constants (B=4, S=1024, H=2048, I=2048, E=8, top_k=2)
#define TT   4096
#define HH   2048
#define EE   8
#define II   2048
#define I2   4096
#define NASS (TT * 2)
#define KDIM 2048
#define BM   128
#define BN   128
#define BK   32
#define NCHUNK (KDIM / BK)   // 64
#define NSTAGE 4
#define STRD 32
#define TILEB (BM * STRD * 2)          // 8192 B per tile
#define STG_T (2 * TILEB)              // 16384 B per stage (A, B)
#define SMEM_DYN (NSTAGE * STG_T)      // 65536 B -> 2 CTAs/SM
#define NPCTA 296                      // persistent CTAs (2 per SM x 148)
#define MAXPAIR 80

#define SWZ(r, cs) ((cs) ^ ((r) & 3))

// ---------------- scratch (device globals) ----------------
__device__ int   g_topk_idx[TT * 2];
__device__ float g_topk_w[TT * 2];
__device__ int   g_cnt[EE];
__device__ int   g_off[EE];
__device__ int   g_cur[EE];
__device__ int   g_rowtok[NASS];
__device__ float g_roww[NASS];
__device__ int   g_pos[TT * 2];
__device__ int   g_pair[MAXPAIR];    // (e<<16) | m_tile
__device__ int   g_P;                // number of (e, m-tile) pairs
__device__ int   g_tick1, g_tick2;   // ticket counters
__device__ __half g_xh[(size_t)TT * HH];
__device__ __half g_w1h[(size_t)EE * I2 * HH];
__device__ __half g_w2h[(size_t)EE * HH * II];
__device__ __half g_act[(size_t)NASS * II];
__device__ float  g_y[(size_t)NASS * HH];

// ---------------- helpers ----------------
__device__ __forceinline__ uint32_t s2u(const void* p) {
    uint32_t a;
    asm("{ .reg .u64 t; cvta.to.shared.u64 t, %1; cvt.u32.u64 %0, t; }" : "=r"(a) : "l"(p));
    return a;
}
__device__ __forceinline__ void cpasync16(uint32_t dst, const void* src) {
    asm volatile("cp.async.cg.shared.global [%0], [%1], 16;" :: "r"(dst), "l"(src));
}
__device__ __forceinline__ void cp_commit() { asm volatile("cp.async.commit_group;"); }
template <int N>
__device__ __forceinline__ void cp_wait() { asm volatile("cp.async.wait_group %0;" :: "n"(N)); }

__device__ __forceinline__ void ldm_x4(uint32_t* r, uint32_t addr) {
    asm volatile("ldmatrix.sync.aligned.m8n8.x4.shared.b16 {%0,%1,%2,%3}, [%4];"
                 : "=r"(r[0]), "=r"(r[1]), "=r"(r[2]), "=r"(r[3]) : "r"(addr));
}
__device__ __forceinline__ void mma16816(float* d, const uint32_t* a, uint32_t b0, uint32_t b1) {
    asm volatile("mma.sync.aligned.m16n8k16.row.col.f32.f16.f16.f32 "
                 "{%0,%1,%2,%3}, {%4,%5,%6,%7}, {%8,%9}, {%0,%1,%2,%3};"
                 : "+f"(d[0]), "+f"(d[1]), "+f"(d[2]), "+f"(d[3])
                 : "r"(a[0]), "r"(a[1]), "r"(a[2]), "r"(a[3]), "r"(b0), "r"(b1));
}
__device__ __forceinline__ uint32_t frag_addr(uint32_t tilebase, int rowbase, int ks, int lane) {
    int row  = rowbase + (lane & 15);
    int cs16 = ks * 2 + (lane >> 4);
    return tilebase + row * (STRD * 2) + SWZ(row, cs16) * 16;
}

// ---------------- convert: fp32 -> fp16 (weights) ----------------
__global__ void convert_h(const float4* __restrict__ src,
                          __half2* __restrict__ h2, size_t n4) {
    size_t stride = (size_t)gridDim.x * blockDim.x;
    for (size_t i = (size_t)blockIdx.x * blockDim.x + threadIdx.x; i < n4; i += stride) {
        float4 v = src[i];
        h2[i * 2 + 0] = __floats2half2_rn(v.x, v.y);
        h2[i * 2 + 1] = __floats2half2_rn(v.z, v.w);
    }
}

// ---------------- routing ----------------
__global__ void zero_counts_kernel() {
    if (threadIdx.x < EE) { g_cnt[threadIdx.x] = 0; g_cur[threadIdx.x] = 0; }
    if (threadIdx.x == 0) { g_tick1 = 0; g_tick2 = 0; }
}

// gate + emit fp16 copy of x
__global__ void gate_kernel(const float* __restrict__ x, const float* __restrict__ gw) {
    int t = blockIdx.x, tid = threadIdx.x;
    float acc[EE];
#pragma unroll
    for (int e = 0; e < EE; e++) acc[e] = 0.f;
#pragma unroll
    for (int i = 0; i < HH / 256; i++) {
        int h = tid + i * 256;
        float xv = x[(size_t)t * HH + h];
        g_xh[(size_t)t * HH + h] = __float2half_rn(xv);
#pragma unroll
        for (int e = 0; e < EE; e++) acc[e] += xv * gw[e * HH + h];
    }
    __shared__ float red[EE][256];
#pragma unroll
    for (int e = 0; e < EE; e++) red[e][tid] = acc[e];
    __syncthreads();
    for (int s = 128; s > 0; s >>= 1) {
        if (tid < s) {
#pragma unroll
            for (int e = 0; e < EE; e++) red[e][tid] += red[e][tid + s];
        }
        __syncthreads();
    }
    if (tid == 0) {
        float lg[EE];
#pragma unroll
        for (int e = 0; e < EE; e++) lg[e] = red[e][0];
        int i1 = 0;
#pragma unroll
        for (int e = 1; e < EE; e++) if (lg[e] > lg[i1]) i1 = e;
        int i2 = -1;
#pragma unroll
        for (int e = 0; e < EE; e++)
            if (e != i1 && (i2 < 0 || lg[e] > lg[i2])) i2 = e;
        float w1 = 1.f / (1.f + expf(lg[i2] - lg[i1]));
        g_topk_idx[t * 2 + 0] = i1; g_topk_idx[t * 2 + 1] = i2;
        g_topk_w[t * 2 + 0] = w1;   g_topk_w[t * 2 + 1] = 1.f - w1;
        atomicAdd(&g_cnt[i1], 1);   atomicAdd(&g_cnt[i2], 1);
    }
}

// offsets + compact (expert, m-tile) pair list
__global__ void scan_kernel() {
    if (threadIdx.x == 0) {
        int s = 0, P = 0;
        for (int e = 0; e < EE; e++) {
            g_off[e] = s;
            int c = g_cnt[e];
            s += c;
            for (int m0 = 0; m0 < c; m0 += BM) g_pair[P++] = (e << 16) | (m0 / BM);
        }
        g_P = P;
    }
}

__global__ void scatter_kernel() {
    int t = blockIdx.x * blockDim.x + threadIdx.x;
    if (t >= TT) return;
#pragma unroll
    for (int k = 0; k < 2; k++) {
        int e = g_topk_idx[t * 2 + k];
        int pos = g_off[e] + atomicAdd(&g_cur[e], 1);
        g_rowtok[pos] = t;
        g_roww[pos]   = g_topk_w[t * 2 + k];
        g_pos[t * 2 + k] = pos;
    }
}

// ---------------- final combine: out[t] = w0*y[p0] + w1*y[p1] ----------------
__global__ void combine_kernel(float* __restrict__ out) {
    int t = blockIdx.x, tid = threadIdx.x;
    int p0 = g_pos[t * 2 + 0], p1 = g_pos[t * 2 + 1];
    float w0 = g_topk_w[t * 2 + 0], w1 = g_topk_w[t * 2 + 1];
    const float4* y0 = (const float4*)(g_y + (size_t)p0 * HH);
    const float4* y1 = (const float4*)(g_y + (size_t)p1 * HH);
    float4* o = (float4*)(out + (size_t)t * HH);
#pragma unroll
    for (int i = 0; i < 2; i++) {
        int c = tid + i * 256;
        float4 a = y0[c], b = y1[c];
        float4 r;
        r.x = w0 * a.x + w1 * b.x;
        r.y = w0 * a.y + w1 * b.y;
        r.z = w0 * a.z + w1 * b.z;
        r.w = w0 * a.w + w1 * b.w;
        o[c] = r;
    }
}

// ---------------- persistent fp16 HMMA GEMM, ticket-scheduled tiles ----------------
// IS_FC1=1: D = x @ w1^T, epilogue bias+SwiGLU -> g_act;  NT=32 N-tiles/pair
// IS_FC1=0: D = act @ w2^T, epilogue bias -> g_y;         NT=16 N-tiles/pair
template <int IS_FC1>
__global__ void __launch_bounds__(256, 2) moe_gemm(
    const float* __restrict__ bias, float* __restrict__ outp)
{
    constexpr int NT = IS_FC1 ? (I2 / BN) : (HH / BN);
    extern __shared__ char dsm[];
    __shared__ int s_row[BM];
    __shared__ int s_t;

    const int NTOT = IS_FC1 ? I2 : HH;
    int tid = threadIdx.x;
    const __half* Ah = IS_FC1 ? g_xh : g_act;
    const __half* Wb = IS_FC1 ? g_w1h : g_w2h;
    int* tick = IS_FC1 ? &g_tick1 : &g_tick2;

    uint32_t smb = s2u(dsm);
    int lane = tid & 31, wid = tid >> 5;
    int wm = (wid & 3) * 32;
    int wn = (wid >> 2) * 64;

    for (;;) {
        if (tid == 0) s_t = atomicAdd(tick, 1);
        __syncthreads();
        int t = s_t;
        if (t >= g_P * NT) break;

        int pe  = g_pair[t / NT];
        int e   = pe >> 16;
        int m0  = (pe & 0xffff) * BM;
        int n0  = (t % NT) * BN;
        int cnt = g_cnt[e];
        int off = g_off[e];
        const __half* Bh = Wb + (size_t)e * NTOT * KDIM;

        if (tid < BM) {
            int m = m0 + tid;
            if (IS_FC1) s_row[tid] = (m < cnt) ? g_rowtok[off + m] : g_rowtok[off];
            else        s_row[tid] = off + ((m < cnt) ? m : cnt - 1);
        }
        __syncthreads();

        size_t aoff[2], boff[2];
        uint32_t dstoff[2];
#pragma unroll
        for (int i = 0; i < 2; i++) {
            int idx = tid + i * 256;
            int r = idx >> 2, cs = idx & 3;
            aoff[i] = (size_t)s_row[r] * KDIM + cs * 8;
            boff[i] = (size_t)(n0 + r) * KDIM + cs * 8;
            dstoff[i] = r * (STRD * 2) + SWZ(r, cs) * 16;
        }

#pragma unroll
        for (int c = 0; c < NSTAGE - 1; c++) {
            uint32_t sb = smb + c * STG_T;
#pragma unroll
            for (int i = 0; i < 2; i++) {
                cpasync16(sb + dstoff[i],         Ah + aoff[i] + c * BK);
                cpasync16(sb + dstoff[i] + TILEB, Bh + boff[i] + c * BK);
            }
            cp_commit();
        }

        float acc[2][8][4];
#pragma unroll
        for (int i = 0; i < 2; i++)
#pragma unroll
            for (int j = 0; j < 8; j++)
#pragma unroll
                for (int k = 0; k < 4; k++) acc[i][j][k] = 0.f;

        int stage = 0;
        for (int c = 0; c < NCHUNK; c++) {
            cp_wait<NSTAGE - 2>();
            __syncthreads();
            uint32_t sb = smb + stage * STG_T;
#pragma unroll
            for (int ks = 0; ks < 2; ks++) {
                uint32_t ah[2][4];
#pragma unroll
                for (int mi = 0; mi < 2; mi++)
                    ldm_x4(ah[mi], frag_addr(sb, wm + mi * 16, ks, lane));
#pragma unroll
                for (int bq = 0; bq < 4; bq++) {
                    uint32_t bh[4];
                    ldm_x4(bh, frag_addr(sb + TILEB, wn + bq * 16, ks, lane));
#pragma unroll
                    for (int mi = 0; mi < 2; mi++) {
                        mma16816(acc[mi][bq * 2 + 0], ah[mi], bh[0], bh[2]);
                        mma16816(acc[mi][bq * 2 + 1], ah[mi], bh[1], bh[3]);
                    }
                }
            }
            int cn = c + NSTAGE - 1;
            if (cn < NCHUNK) {
                uint32_t sb2 = smb + (cn % NSTAGE) * STG_T;
#pragma unroll
                for (int i = 0; i < 2; i++) {
                    cpasync16(sb2 + dstoff[i],         Ah + aoff[i] + (size_t)cn * BK);
                    cpasync16(sb2 + dstoff[i] + TILEB, Bh + boff[i] + (size_t)cn * BK);
                }
            }
            cp_commit();
            stage = (stage + 1 == NSTAGE) ? 0 : stage + 1;
        }

        // -------- epilogue --------
#pragma unroll
        for (int mi = 0; mi < 2; mi++) {
#pragma unroll
            for (int h = 0; h < 2; h++) {
                int m = m0 + wm + mi * 16 + (lane >> 2) + h * 8;
                if (m >= cnt) continue;
                if (IS_FC1) {
                    size_t rowo = (size_t)(off + m) * II;
#pragma unroll
                    for (int nb = 0; nb < 8; nb++) {
                        int f = n0 + wn + nb * 8 + (lane & 3) * 2;
                        float g = acc[mi][nb][h * 2 + 0] + bias[(size_t)e * NTOT + f];
                        float l = acc[mi][nb][h * 2 + 1] + bias[(size_t)e * NTOT + f + 1];
                        float sg = 1.f / (1.f + __expf(-1.702f * g));
                        g_act[rowo + (f >> 1)] = __float2half_rn(g * sg * (l + 1.f));
                    }
                } else {
                    size_t rowo = (size_t)(off + m) * HH;
#pragma unroll
                    for (int nb = 0; nb < 8; nb++) {
                        int f = n0 + wn + nb * 8 + (lane & 3) * 2;
                        g_y[rowo + f]     = acc[mi][nb][h * 2 + 0] + bias[(size_t)e * NTOT + f];
                        g_y[rowo + f + 1] = acc[mi][nb][h * 2 + 1] + bias[(size_t)e * NTOT + f + 1];
                    }
                }
            }
        }
        // drain pipeline before next tile reuses stages / s_row
        cp_wait<0>();
        __syncthreads();
    }
}

// ---------------- launch ----------------
extern "C" void kernel_launch(void* const* d_in, const int* in_sizes, int n_in,
                              void* d_out, int out_size) {
    const float* x  = (const float*)d_in[0];
    const float* gw = (const float*)d_in[1];
    const float* w1 = (const float*)d_in[2];
    const float* b1 = (const float*)d_in[3];
    const float* w2 = (const float*)d_in[4];
    const float* b2 = (const float*)d_in[5];
    float* out = (float*)d_out;

    cudaFuncSetAttribute(moe_gemm<1>, cudaFuncAttributeMaxDynamicSharedMemorySize, SMEM_DYN);
    cudaFuncSetAttribute(moe_gemm<0>, cudaFuncAttributeMaxDynamicSharedMemorySize, SMEM_DYN);

    __half2 *w1h, *w2h;
    cudaGetSymbolAddress((void**)&w1h, g_w1h);
    cudaGetSymbolAddress((void**)&w2h, g_w2h);

    convert_h<<<4096, 256>>>((const float4*)w1, w1h, (size_t)EE * I2 * HH / 4);
    convert_h<<<4096, 256>>>((const float4*)w2, w2h, (size_t)EE * HH * II / 4);
    zero_counts_kernel<<<1, 32>>>();
    gate_kernel<<<TT, 256>>>(x, gw);
    scan_kernel<<<1, 32>>>();
    scatter_kernel<<<(TT + 255) / 256, 256>>>();
    moe_gemm<1><<<NPCTA, 256, SMEM_DYN>>>(b1, nullptr);
    moe_gemm<0><<<NPCTA, 256, SMEM_DYN>>>(b2, out);
    combine_kernel<<<TT, 256>>>(out);
}

// round 17
// speedup vs baseline: 1.2977x; 1.2977x over previous
#include <cuda_runtime.h>
#include <cuda_fp16.h>
#include <cstdint>
#include <math.h>

// Problem constants (B=4, S=1024, H=2048, I=2048, E=8, top_k=2)
#define TT   4096
#define HH   2048
#define EE   8
#define II   2048
#define I2   4096
#define NASS (TT * 2)
#define KDIM 2048
#define BM   128
#define BN   128
#define BK   32
#define NCHUNK (KDIM / BK)   // 64
#define NSTAGE 4
#define STRD 32
#define TILEB (BM * STRD * 2)          // 8192 B per tile
#define STG_T (2 * TILEB)              // 16384 B per stage (A, B)
#define SMEM_DYN (NSTAGE * STG_T)      // 65536 B -> 2 CTAs/SM
#define MAXPAIR 71                     // max (expert, m-tile) pairs

#define SWZ(r, cs) ((cs) ^ ((r) & 3))

// ---------------- scratch (device globals) ----------------
__device__ int   g_topk_idx[TT * 2];
__device__ float g_topk_w[TT * 2];
__device__ int   g_cnt[EE];
__device__ int   g_off[EE];
__device__ int   g_cur[EE];
__device__ int   g_rowtok[NASS];
__device__ float g_roww[NASS];
__device__ int   g_pos[TT * 2];
__device__ int   g_pair[MAXPAIR + 1];   // (e<<16) | m_tile
__device__ int   g_P;
__device__ __half g_xh[(size_t)TT * HH];
__device__ __half g_w1h[(size_t)EE * I2 * HH];
__device__ __half g_w2h[(size_t)EE * HH * II];
__device__ __half g_act[(size_t)NASS * II];
__device__ float  g_y[(size_t)NASS * HH];

// ---------------- helpers ----------------
__device__ __forceinline__ uint32_t s2u(const void* p) {
    uint32_t a;
    asm("{ .reg .u64 t; cvta.to.shared.u64 t, %1; cvt.u32.u64 %0, t; }" : "=r"(a) : "l"(p));
    return a;
}
__device__ __forceinline__ void cpasync16(uint32_t dst, const void* src) {
    asm volatile("cp.async.cg.shared.global [%0], [%1], 16;" :: "r"(dst), "l"(src));
}
__device__ __forceinline__ void cp_commit() { asm volatile("cp.async.commit_group;"); }
template <int N>
__device__ __forceinline__ void cp_wait() { asm volatile("cp.async.wait_group %0;" :: "n"(N)); }

__device__ __forceinline__ void ldm_x4(uint32_t* r, uint32_t addr) {
    asm volatile("ldmatrix.sync.aligned.m8n8.x4.shared.b16 {%0,%1,%2,%3}, [%4];"
                 : "=r"(r[0]), "=r"(r[1]), "=r"(r[2]), "=r"(r[3]) : "r"(addr));
}
__device__ __forceinline__ void mma16816(float* d, const uint32_t* a, uint32_t b0, uint32_t b1) {
    asm volatile("mma.sync.aligned.m16n8k16.row.col.f32.f16.f16.f32 "
                 "{%0,%1,%2,%3}, {%4,%5,%6,%7}, {%8,%9}, {%0,%1,%2,%3};"
                 : "+f"(d[0]), "+f"(d[1]), "+f"(d[2]), "+f"(d[3])
                 : "r"(a[0]), "r"(a[1]), "r"(a[2]), "r"(a[3]), "r"(b0), "r"(b1));
}
__device__ __forceinline__ uint32_t frag_addr(uint32_t tilebase, int rowbase, int ks, int lane) {
    int row  = rowbase + (lane & 15);
    int cs16 = ks * 2 + (lane >> 4);
    return tilebase + row * (STRD * 2) + SWZ(row, cs16) * 16;
}

// ---------------- convert: fp32 -> fp16 (weights) ----------------
__global__ void convert_h(const float4* __restrict__ src,
                          __half2* __restrict__ h2, size_t n4) {
    size_t stride = (size_t)gridDim.x * blockDim.x;
    for (size_t i = (size_t)blockIdx.x * blockDim.x + threadIdx.x; i < n4; i += stride) {
        float4 v = src[i];
        h2[i * 2 + 0] = __floats2half2_rn(v.x, v.y);
        h2[i * 2 + 1] = __floats2half2_rn(v.z, v.w);
    }
}

// ---------------- routing ----------------
__global__ void zero_counts_kernel() {
    if (threadIdx.x < EE) { g_cnt[threadIdx.x] = 0; g_cur[threadIdx.x] = 0; }
}

// gate + emit fp16 copy of x
__global__ void gate_kernel(const float* __restrict__ x, const float* __restrict__ gw) {
    int t = blockIdx.x, tid = threadIdx.x;
    float acc[EE];
#pragma unroll
    for (int e = 0; e < EE; e++) acc[e] = 0.f;
#pragma unroll
    for (int i = 0; i < HH / 256; i++) {
        int h = tid + i * 256;
        float xv = x[(size_t)t * HH + h];
        g_xh[(size_t)t * HH + h] = __float2half_rn(xv);
#pragma unroll
        for (int e = 0; e < EE; e++) acc[e] += xv * gw[e * HH + h];
    }
    __shared__ float red[EE][256];
#pragma unroll
    for (int e = 0; e < EE; e++) red[e][tid] = acc[e];
    __syncthreads();
    for (int s = 128; s > 0; s >>= 1) {
        if (tid < s) {
#pragma unroll
            for (int e = 0; e < EE; e++) red[e][tid] += red[e][tid + s];
        }
        __syncthreads();
    }
    if (tid == 0) {
        float lg[EE];
#pragma unroll
        for (int e = 0; e < EE; e++) lg[e] = red[e][0];
        int i1 = 0;
#pragma unroll
        for (int e = 1; e < EE; e++) if (lg[e] > lg[i1]) i1 = e;
        int i2 = -1;
#pragma unroll
        for (int e = 0; e < EE; e++)
            if (e != i1 && (i2 < 0 || lg[e] > lg[i2])) i2 = e;
        float w1 = 1.f / (1.f + expf(lg[i2] - lg[i1]));
        g_topk_idx[t * 2 + 0] = i1; g_topk_idx[t * 2 + 1] = i2;
        g_topk_w[t * 2 + 0] = w1;   g_topk_w[t * 2 + 1] = 1.f - w1;
        atomicAdd(&g_cnt[i1], 1);   atomicAdd(&g_cnt[i2], 1);
    }
}

// offsets + compact (expert, m-tile) pair list
__global__ void scan_kernel() {
    if (threadIdx.x == 0) {
        int s = 0, P = 0;
        for (int e = 0; e < EE; e++) {
            g_off[e] = s;
            int c = g_cnt[e];
            s += c;
            for (int m0 = 0; m0 < c; m0 += BM) g_pair[P++] = (e << 16) | (m0 / BM);
        }
        g_P = P;
    }
}

__global__ void scatter_kernel() {
    int t = blockIdx.x * blockDim.x + threadIdx.x;
    if (t >= TT) return;
#pragma unroll
    for (int k = 0; k < 2; k++) {
        int e = g_topk_idx[t * 2 + k];
        int pos = g_off[e] + atomicAdd(&g_cur[e], 1);
        g_rowtok[pos] = t;
        g_roww[pos]   = g_topk_w[t * 2 + k];
        g_pos[t * 2 + k] = pos;
    }
}

// ---------------- final combine: out[t] = w0*y[p0] + w1*y[p1] ----------------
__global__ void combine_kernel(float* __restrict__ out) {
    int t = blockIdx.x, tid = threadIdx.x;
    int p0 = g_pos[t * 2 + 0], p1 = g_pos[t * 2 + 1];
    float w0 = g_topk_w[t * 2 + 0], w1 = g_topk_w[t * 2 + 1];
    const float4* y0 = (const float4*)(g_y + (size_t)p0 * HH);
    const float4* y1 = (const float4*)(g_y + (size_t)p1 * HH);
    float4* o = (float4*)(out + (size_t)t * HH);
#pragma unroll
    for (int i = 0; i < 2; i++) {
        int c = tid + i * 256;
        float4 a = y0[c], b = y1[c];
        float4 r;
        r.x = w0 * a.x + w1 * b.x;
        r.y = w0 * a.y + w1 * b.y;
        r.z = w0 * a.z + w1 * b.z;
        r.w = w0 * a.w + w1 * b.w;
        o[c] = r;
    }
}

// ---------------- fp16 HMMA GEMM, cp.async 4-stage, 2 CTAs/SM ----------------
// grid: (N-tiles, MAXPAIR). blockIdx.y indexes compact pair list; y >= g_P exits.
// IS_FC1=1: D = x @ w1^T, epilogue bias+SwiGLU -> g_act
// IS_FC1=0: D = act @ w2^T, epilogue bias -> g_y
template <int IS_FC1>
__global__ void __launch_bounds__(256, 2) moe_gemm(
    const float* __restrict__ bias, float* __restrict__ outp)
{
    extern __shared__ char dsm[];
    __shared__ int s_row[BM];

    if (blockIdx.y >= (unsigned)g_P) return;
    int pe  = g_pair[blockIdx.y];
    int e   = pe >> 16;
    int m0  = (pe & 0xffff) * BM;
    int n0  = blockIdx.x * BN;
    int cnt = g_cnt[e];
    int off = g_off[e];
    const int NTOT = IS_FC1 ? I2 : HH;
    int tid = threadIdx.x;

    const __half* Ah = IS_FC1 ? g_xh : g_act;
    const __half* Bh = (IS_FC1 ? g_w1h : g_w2h) + (size_t)e * NTOT * KDIM;

    if (tid < BM) {
        int m = m0 + tid;
        if (IS_FC1) s_row[tid] = (m < cnt) ? g_rowtok[off + m] : g_rowtok[off];
        else        s_row[tid] = off + ((m < cnt) ? m : cnt - 1);
    }
    __syncthreads();

    uint32_t smb = s2u(dsm);

    size_t aoff[2], boff[2];
    uint32_t dstoff[2];
#pragma unroll
    for (int i = 0; i < 2; i++) {
        int idx = tid + i * 256;
        int r = idx >> 2, cs = idx & 3;
        aoff[i] = (size_t)s_row[r] * KDIM + cs * 8;
        boff[i] = (size_t)(n0 + r) * KDIM + cs * 8;
        dstoff[i] = r * (STRD * 2) + SWZ(r, cs) * 16;
    }

#pragma unroll
    for (int c = 0; c < NSTAGE - 1; c++) {
        uint32_t sb = smb + c * STG_T;
#pragma unroll
        for (int i = 0; i < 2; i++) {
            cpasync16(sb + dstoff[i],         Ah + aoff[i] + c * BK);
            cpasync16(sb + dstoff[i] + TILEB, Bh + boff[i] + c * BK);
        }
        cp_commit();
    }

    int lane = tid & 31, wid = tid >> 5;
    int wm = (wid & 3) * 32;
    int wn = (wid >> 2) * 64;

    float acc[2][8][4];
#pragma unroll
    for (int i = 0; i < 2; i++)
#pragma unroll
        for (int j = 0; j < 8; j++)
#pragma unroll
            for (int k = 0; k < 4; k++) acc[i][j][k] = 0.f;

    int stage = 0;
    for (int c = 0; c < NCHUNK; c++) {
        cp_wait<NSTAGE - 2>();
        __syncthreads();
        uint32_t sb = smb + stage * STG_T;
#pragma unroll
        for (int ks = 0; ks < 2; ks++) {
            uint32_t ah[2][4];
#pragma unroll
            for (int mi = 0; mi < 2; mi++)
                ldm_x4(ah[mi], frag_addr(sb, wm + mi * 16, ks, lane));
#pragma unroll
            for (int bq = 0; bq < 4; bq++) {
                uint32_t bh[4];
                ldm_x4(bh, frag_addr(sb + TILEB, wn + bq * 16, ks, lane));
#pragma unroll
                for (int mi = 0; mi < 2; mi++) {
                    mma16816(acc[mi][bq * 2 + 0], ah[mi], bh[0], bh[2]);
                    mma16816(acc[mi][bq * 2 + 1], ah[mi], bh[1], bh[3]);
                }
            }
        }
        int cn = c + NSTAGE - 1;
        if (cn < NCHUNK) {
            uint32_t sb2 = smb + (cn % NSTAGE) * STG_T;
#pragma unroll
            for (int i = 0; i < 2; i++) {
                cpasync16(sb2 + dstoff[i],         Ah + aoff[i] + (size_t)cn * BK);
                cpasync16(sb2 + dstoff[i] + TILEB, Bh + boff[i] + (size_t)cn * BK);
            }
        }
        cp_commit();
        stage = (stage + 1 == NSTAGE) ? 0 : stage + 1;
    }

    // -------- epilogue --------
#pragma unroll
    for (int mi = 0; mi < 2; mi++) {
#pragma unroll
        for (int h = 0; h < 2; h++) {
            int m = m0 + wm + mi * 16 + (lane >> 2) + h * 8;
            if (m >= cnt) continue;
            if (IS_FC1) {
                size_t rowo = (size_t)(off + m) * II;
#pragma unroll
                for (int nb = 0; nb < 8; nb++) {
                    int f = n0 + wn + nb * 8 + (lane & 3) * 2;
                    float g = acc[mi][nb][h * 2 + 0] + bias[(size_t)e * NTOT + f];
                    float l = acc[mi][nb][h * 2 + 1] + bias[(size_t)e * NTOT + f + 1];
                    float sg = 1.f / (1.f + __expf(-1.702f * g));
                    g_act[rowo + (f >> 1)] = __float2half_rn(g * sg * (l + 1.f));
                }
            } else {
                size_t rowo = (size_t)(off + m) * HH;
#pragma unroll
                for (int nb = 0; nb < 8; nb++) {
                    int f = n0 + wn + nb * 8 + (lane & 3) * 2;
                    g_y[rowo + f]     = acc[mi][nb][h * 2 + 0] + bias[(size_t)e * NTOT + f];
                    g_y[rowo + f + 1] = acc[mi][nb][h * 2 + 1] + bias[(size_t)e * NTOT + f + 1];
                }
            }
        }
    }
}

// ---------------- launch ----------------
extern "C" void kernel_launch(void* const* d_in, const int* in_sizes, int n_in,
                              void* d_out, int out_size) {
    const float* x  = (const float*)d_in[0];
    const float* gw = (const float*)d_in[1];
    const float* w1 = (const float*)d_in[2];
    const float* b1 = (const float*)d_in[3];
    const float* w2 = (const float*)d_in[4];
    const float* b2 = (const float*)d_in[5];
    float* out = (float*)d_out;

    cudaFuncSetAttribute(moe_gemm<1>, cudaFuncAttributeMaxDynamicSharedMemorySize, SMEM_DYN);
    cudaFuncSetAttribute(moe_gemm<0>, cudaFuncAttributeMaxDynamicSharedMemorySize, SMEM_DYN);

    __half2 *w1h, *w2h;
    cudaGetSymbolAddress((void**)&w1h, g_w1h);
    cudaGetSymbolAddress((void**)&w2h, g_w2h);

    convert_h<<<4096, 256>>>((const float4*)w1, w1h, (size_t)EE * I2 * HH / 4);
    convert_h<<<4096, 256>>>((const float4*)w2, w2h, (size_t)EE * HH * II / 4);
    zero_counts_kernel<<<1, 32>>>();
    gate_kernel<<<TT, 256>>>(x, gw);
    scan_kernel<<<1, 32>>>();
    scatter_kernel<<<(TT + 255) / 256, 256>>>();
    moe_gemm<1><<<dim3(I2 / BN, MAXPAIR), 256, SMEM_DYN>>>(b1, nullptr);
    moe_gemm<0><<<dim3(HH / BN, MAXPAIR), 256, SMEM_DYN>>>(b2, out);
    combine_kernel<<<TT, 256>>>(out);
}